// round 7
// baseline (speedup 1.0000x reference)
#include <cuda_runtime.h>
#include <stdint.h>

#define NQ 10
#define BSZ 32768
#define NT 256
#define INV254 (1.0f/254.0f)

__device__ char  g_X [2][NT][8192];        // [dig][tile][128r x 64B, sw64]
__device__ char  g_W1[NQ][2][16384];       // [net][dig][256c x 64B, sw64]
__device__ char  g_W2[NQ][4][2][2][8192];  // [net][np][kh][dig][64n x 128kb, sw128]
__device__ float g_SX[BSZ];
__device__ float g_SW1[NQ][256];
__device__ float g_SW2[NQ][256];

__device__ __forceinline__ uint32_t smem_u32(const void* p){
    uint32_t a; asm("{ .reg .u64 t; cvta.to.shared.u64 t, %1; cvt.u32.u64 %0, t; }":"=r"(a):"l"(p)); return a;
}
__device__ __forceinline__ uint32_t sw128(uint32_t o){ return o ^ ((o>>3)&0x70); }
__device__ __forceinline__ uint32_t sw64 (uint32_t o){ return o ^ ((o>>3)&0x30); }
__device__ __forceinline__ void cpa16(uint32_t d, const void* s){
    asm volatile("cp.async.cg.shared.global [%0], [%1], 16;"::"r"(d),"l"(s):"memory");
}
#define CP_COMMIT() asm volatile("cp.async.commit_group;":::"memory")
#define CP_WAIT(n)  asm volatile("cp.async.wait_group %0;"::"n"(n):"memory")
__device__ __forceinline__ void ldm4(uint32_t r[4], uint32_t a){
    asm volatile("ldmatrix.sync.aligned.m8n8.x4.shared.b16 {%0,%1,%2,%3}, [%4];"
        :"=r"(r[0]),"=r"(r[1]),"=r"(r[2]),"=r"(r[3]):"r"(a));
}
__device__ __forceinline__ void imma(int c[4], const uint32_t a[4], uint32_t b0, uint32_t b1){
    asm volatile("mma.sync.aligned.m16n8k32.row.col.s32.s8.s8.s32 "
        "{%0,%1,%2,%3},{%4,%5,%6,%7},{%8,%9},{%0,%1,%2,%3};"
        :"+r"(c[0]),"+r"(c[1]),"+r"(c[2]),"+r"(c[3])
        :"r"(a[0]),"r"(a[1]),"r"(a[2]),"r"(a[3]),"r"(b0),"r"(b1));
}

// ===================== prep =====================
__global__ void __launch_bounds__(128) prep_x(const float* __restrict__ st, const float* __restrict__ ac){
    int t=blockIdx.x, r=threadIdx.x, R=t*128+r;
    float v[32], mx=1e-20f;
    #pragma unroll
    for(int k=0;k<32;k++){
        float x=0.f;
        if(k<17)x=st[R*17+k]; else if(k<23)x=ac[R*6+k-17];
        v[k]=x; mx=fmaxf(mx,fabsf(x));
    }
    g_SX[R]=mx*(1.f/127.f);
    float inv=127.f/mx;
    uint32_t w[2][8]={};
    #pragma unroll
    for(int k=0;k<32;k++){
        float u=v[k]*inv; int a=__float2int_rn(u); int b=__float2int_rn((u-(float)a)*254.f);
        w[0][k>>2]|=(uint32_t)(a&255)<<((k&3)*8);
        w[1][k>>2]|=(uint32_t)(b&255)<<((k&3)*8);
    }
    #pragma unroll
    for(int d=0;d<2;d++){
        char* b=&g_X[d][t][0];
        *(uint4*)(b+sw64(r*64+0 ))=make_uint4(w[d][0],w[d][1],w[d][2],w[d][3]);
        *(uint4*)(b+sw64(r*64+16))=make_uint4(w[d][4],w[d][5],w[d][6],w[d][7]);
        *(uint4*)(b+sw64(r*64+32))=make_uint4(0,0,0,0);
        *(uint4*)(b+sw64(r*64+48))=make_uint4(0,0,0,0);
    }
}
__global__ void __launch_bounds__(256) prep_w1(const float* __restrict__ W1){
    int n=blockIdx.x, c=threadIdx.x;
    float v[32], mx=1e-20f;
    #pragma unroll
    for(int k=0;k<32;k++){
        float x=(k<23)?W1[(n*23+k)*256+c]:0.f;
        v[k]=x; mx=fmaxf(mx,fabsf(x));
    }
    g_SW1[n][c]=mx*(1.f/127.f);
    float inv=127.f/mx;
    uint32_t w[2][8]={};
    #pragma unroll
    for(int k=0;k<32;k++){
        float u=v[k]*inv; int a=__float2int_rn(u); int b=__float2int_rn((u-(float)a)*254.f);
        w[0][k>>2]|=(uint32_t)(a&255)<<((k&3)*8);
        w[1][k>>2]|=(uint32_t)(b&255)<<((k&3)*8);
    }
    #pragma unroll
    for(int d=0;d<2;d++){
        char* b=&g_W1[n][d][0];
        *(uint4*)(b+sw64(c*64+0 ))=make_uint4(w[d][0],w[d][1],w[d][2],w[d][3]);
        *(uint4*)(b+sw64(c*64+16))=make_uint4(w[d][4],w[d][5],w[d][6],w[d][7]);
        *(uint4*)(b+sw64(c*64+32))=make_uint4(0,0,0,0);
        *(uint4*)(b+sw64(c*64+48))=make_uint4(0,0,0,0);
    }
}
__global__ void __launch_bounds__(256) prep_w2(const float* __restrict__ W2){
    int n=blockIdx.x, c=threadIdx.x;
    const float* src=W2+n*65536+c;
    float mx=1e-20f;
    for(int k=0;k<256;k++) mx=fmaxf(mx,fabsf(src[k*256]));
    g_SW2[n][c]=mx*(1.f/127.f);
    float inv=127.f/mx;
    int np=c>>6, nl=c&63;
    for(int k4=0;k4<64;k4++){
        uint32_t w0=0,w1=0;
        #pragma unroll
        for(int j=0;j<4;j++){
            float u=src[(k4*4+j)*256]*inv;
            int a=__float2int_rn(u); int b=__float2int_rn((u-(float)a)*254.f);
            w0|=(uint32_t)(a&255)<<(j*8); w1|=(uint32_t)(b&255)<<(j*8);
        }
        int kh=(k4*4)>>7, kb=(k4*4)&127;
        uint32_t off=sw128((uint32_t)(nl*128+kb));
        *(uint32_t*)(&g_W2[n][np][kh][0][0]+off)=w0;
        *(uint32_t*)(&g_W2[n][np][kh][1][0]+off)=w1;
    }
}

// ===================== main =====================
#define SM_X    0
#define SM_W1   16384
#define SM_A2   49152      // [dig(32768)][kh(16384)]
#define SM_RING 114688     // 3 x 16384
#define SM_SXs  163840
#define SM_SW1s 164352
#define SM_B1s  165376
#define SM_SW2s 166400
#define SM_B2s  167424
#define SM_W3s  168448
#define SM_SH   169472     // [kh][128]
#define SM_PMX  170496     // [wn][128]
#define SM_RED  171520     // [wn][128]
#define SM_TOT  172544

__global__ void __launch_bounds__(256,1)
qmain(const float* __restrict__ b1,const float* __restrict__ b2,
      const float* __restrict__ W3,const float* __restrict__ b3,float* __restrict__ out){
    extern __shared__ char sm[];
    float* f=(float*)sm;
    const uint32_t sb=smem_u32(sm);
    const int tid=threadIdx.x, wid=tid>>5, lane=tid&31;
    const int tile=blockIdx.x, n=blockIdx.y;
    const int wm=wid&3, wn=wid>>2, Rw=wm*32;
    const int aRow=(lane&7)+((lane>>3)&1)*8, aColB=(lane>>4)*16;
    const int bRow=(lane&7)+((lane>>4)<<3),  bColB=((lane>>3)&1)*16;
    const int q=lane>>2, s2=(lane&3)*2;

    // stage X, W1 images + scalar tables
    for(int d=0;d<2;d++){
        const char* s=&g_X[d][tile][0];
        for(int i=tid;i<512;i+=256) cpa16(sb+SM_X+d*8192+i*16, s+i*16);
        const char* w=&g_W1[n][d][0];
        for(int i=tid;i<1024;i+=256) cpa16(sb+SM_W1+d*16384+i*16, w+i*16);
    }
    CP_COMMIT();
    if(tid<128) f[SM_SXs/4+tid]=g_SX[tile*128+tid];
    f[SM_SW1s/4+tid]=g_SW1[n][tid];
    f[SM_B1s/4+tid]=b1[n*256+tid];
    f[SM_SW2s/4+tid]=g_SW2[n][tid];
    f[SM_B2s/4+tid]=b2[n*256+tid];
    f[SM_W3s/4+tid]=W3[n*256+tid];
    CP_WAIT(0);
    __syncthreads();

    // ---- layer 1: two half-N passes ----
    #pragma unroll 1
    for(int h=0;h<2;h++){
        int P[2][8][4], Q[2][8][4];
        #pragma unroll
        for(int mt=0;mt<2;mt++)
            #pragma unroll
            for(int nt=0;nt<8;nt++)
                #pragma unroll
                for(int e=0;e<4;e++){P[mt][nt][e]=0;Q[mt][nt][e]=0;}
        uint32_t a0[2][4],a1[2][4];
        #pragma unroll
        for(int mt=0;mt<2;mt++){
            uint32_t o=sw64((uint32_t)((Rw+mt*16+aRow)*64+aColB));
            ldm4(a0[mt], sb+SM_X+o);
            ldm4(a1[mt], sb+SM_X+8192+o);
        }
        #pragma unroll
        for(int p=0;p<4;p++){
            int n0=h*128+wn*64+p*16;
            uint32_t o=sw64((uint32_t)((n0+bRow)*64+bColB));
            uint32_t bh[4],bl[4];
            ldm4(bh, sb+SM_W1+o);
            ldm4(bl, sb+SM_W1+16384+o);
            #pragma unroll
            for(int mt=0;mt<2;mt++)
                #pragma unroll
                for(int sub=0;sub<2;sub++){
                    int nt=p*2+sub;
                    imma(P[mt][nt],a0[mt],bh[sub*2],bh[sub*2+1]);
                    imma(Q[mt][nt],a0[mt],bl[sub*2],bl[sub*2+1]);
                    imma(Q[mt][nt],a1[mt],bh[sub*2],bh[sub*2+1]);
                }
        }
        // fold to relu'd f32 (in-place in P), track per-row local max
        float lmax[4]={0.f,0.f,0.f,0.f};
        #pragma unroll
        for(int mt=0;mt<2;mt++)
            #pragma unroll
            for(int nt=0;nt<8;nt++)
                #pragma unroll
                for(int e=0;e<4;e++){
                    int c=h*128+wn*64+nt*8+s2+(e&1);
                    int row=Rw+mt*16+(e>>1)*8+q;
                    float vv=f[SM_SXs/4+row]*f[SM_SW1s/4+c]*
                             ((float)P[mt][nt][e]+(float)Q[mt][nt][e]*INV254)+f[SM_B1s/4+c];
                    vv=fmaxf(vv,0.f);
                    P[mt][nt][e]=__float_as_int(vv);
                    lmax[mt*2+(e>>1)]=fmaxf(lmax[mt*2+(e>>1)],vv);
                }
        #pragma unroll
        for(int i=0;i<4;i++){
            float v=lmax[i];
            v=fmaxf(v,__shfl_xor_sync(0xffffffffu,v,1));
            v=fmaxf(v,__shfl_xor_sync(0xffffffffu,v,2));
            lmax[i]=v;
        }
        if((lane&3)==0){
            #pragma unroll
            for(int i=0;i<4;i++)
                f[SM_PMX/4+wn*128+Rw+(i>>1)*16+(i&1)*8+q]=lmax[i];
        }
        __syncthreads();
        #pragma unroll
        for(int mt=0;mt<2;mt++)
            #pragma unroll
            for(int hh=0;hh<2;hh++){
                int row=Rw+mt*16+hh*8+q;
                float rmx=fmaxf(fmaxf(f[SM_PMX/4+row],f[SM_PMX/4+128+row]),1e-20f);
                if(wn==0&&(lane&3)==0) f[SM_SH/4+h*128+row]=rmx*(1.f/127.f);
                float inv=127.f/rmx;
                #pragma unroll
                for(int nt=0;nt<8;nt++){
                    int kb=wn*64+nt*8+s2;
                    float v0=__int_as_float(P[mt][nt][hh*2+0])*inv;
                    float v1=__int_as_float(P[mt][nt][hh*2+1])*inv;
                    int a=__float2int_rn(v0), b=__float2int_rn(v1);
                    int a2=__float2int_rn((v0-(float)a)*254.f), b2v=__float2int_rn((v1-(float)b)*254.f);
                    uint32_t off=sw128((uint32_t)(row*128+kb));
                    *(uint16_t*)(sm+SM_A2+h*16384+off)=(uint16_t)((a&255)|((b&255)<<8));
                    *(uint16_t*)(sm+SM_A2+32768+h*16384+off)=(uint16_t)((a2&255)|((b2v&255)<<8));
                }
            }
        __syncthreads();
    }

    // ring prologue: stages 0,1
    {
        const char* s0=&g_W2[n][0][0][0][0];
        for(int i=tid;i<1024;i+=256) cpa16(sb+SM_RING+i*16,s0+i*16);
        CP_COMMIT();
        const char* s1=&g_W2[n][0][1][0][0];
        for(int i=tid;i<1024;i+=256) cpa16(sb+SM_RING+16384+i*16,s1+i*16);
        CP_COMMIT();
    }

    // ---- layer 2+3: 8 stages (np 0..3 x kh 0..1) ----
    float rowsum[4]={0.f,0.f,0.f,0.f};
    float accF[2][4][4];
    #pragma unroll 1
    for(int s=0;s<8;s++){
        const int np=s>>1, kh=s&1;
        if(s<7) CP_WAIT(1); else CP_WAIT(0);
        __syncthreads();
        if(s<6){
            const char* src=&g_W2[n][(s+2)>>1][(s+2)&1][0][0];
            uint32_t d=sb+SM_RING+(uint32_t)(((s+2)%3)*16384);
            for(int i=tid;i<1024;i+=256) cpa16(d+i*16,src+i*16);
            CP_COMMIT();
        }
        int P[2][4][4],Q[2][4][4];
        #pragma unroll
        for(int mt=0;mt<2;mt++)
            #pragma unroll
            for(int nt=0;nt<4;nt++)
                #pragma unroll
                for(int e=0;e<4;e++){P[mt][nt][e]=0;Q[mt][nt][e]=0;}
        const uint32_t ring=sb+SM_RING+(uint32_t)((s%3)*16384);
        #pragma unroll
        for(int ks=0;ks<4;ks++){
            uint32_t a0[2][4],a1[2][4];
            #pragma unroll
            for(int mt=0;mt<2;mt++){
                uint32_t o=sw128((uint32_t)((Rw+mt*16+aRow)*128+ks*32+aColB));
                ldm4(a0[mt], sb+SM_A2+kh*16384+o);
                ldm4(a1[mt], sb+SM_A2+32768+kh*16384+o);
            }
            #pragma unroll
            for(int p=0;p<2;p++){
                int nl=wn*32+p*16;
                uint32_t o=sw128((uint32_t)((nl+bRow)*128+ks*32+bColB));
                uint32_t bh[4],bl[4];
                ldm4(bh, ring+o);
                ldm4(bl, ring+8192+o);
                #pragma unroll
                for(int mt=0;mt<2;mt++)
                    #pragma unroll
                    for(int sub=0;sub<2;sub++){
                        int nt=p*2+sub;
                        imma(P[mt][nt],a0[mt],bh[sub*2],bh[sub*2+1]);
                        imma(Q[mt][nt],a0[mt],bl[sub*2],bl[sub*2+1]);
                        imma(Q[mt][nt],a1[mt],bh[sub*2],bh[sub*2+1]);
                    }
            }
        }
        // fold with per-(row,kh) h1 scale and per-col W2 scale
        #pragma unroll
        for(int mt=0;mt<2;mt++)
            #pragma unroll
            for(int nt=0;nt<4;nt++)
                #pragma unroll
                for(int e=0;e<4;e++){
                    int c=np*64+wn*32+nt*8+s2+(e&1);
                    int row=Rw+mt*16+(e>>1)*8+q;
                    float v=f[SM_SH/4+kh*128+row]*f[SM_SW2s/4+c]*
                            ((float)P[mt][nt][e]+(float)Q[mt][nt][e]*INV254);
                    if(kh==0) accF[mt][nt][e]=v;
                    else{
                        float t2=accF[mt][nt][e]+v+f[SM_B2s/4+c];
                        rowsum[mt*2+(e>>1)]+=fmaxf(t2,0.f)*f[SM_W3s/4+c];
                    }
                }
    }

    #pragma unroll
    for(int i=0;i<4;i++){
        float v=rowsum[i];
        v+=__shfl_xor_sync(0xffffffffu,v,1);
        v+=__shfl_xor_sync(0xffffffffu,v,2);
        if((lane&3)==0) f[SM_RED/4+wn*128+Rw+(i>>1)*16+(i&1)*8+q]=v;
    }
    __syncthreads();
    if(tid<128)
        out[n*BSZ+tile*128+tid]=f[SM_RED/4+tid]+f[SM_RED/4+128+tid]+b3[n];
}

extern "C" void kernel_launch(void* const* d_in, const int* in_sizes, int n_in,
                              void* d_out, int out_size){
    const float* state =(const float*)d_in[0];
    const float* action=(const float*)d_in[1];
    const float* W1=(const float*)d_in[2];
    const float* b1=(const float*)d_in[3];
    const float* W2=(const float*)d_in[4];
    const float* b2=(const float*)d_in[5];
    const float* W3=(const float*)d_in[6];
    const float* b3=(const float*)d_in[7];
    float* out=(float*)d_out;

    prep_x<<<NT,128>>>(state,action);
    prep_w1<<<NQ,256>>>(W1);
    prep_w2<<<NQ,256>>>(W2);

    cudaFuncSetAttribute(qmain,cudaFuncAttributeMaxDynamicSharedMemorySize,SM_TOT);
    dim3 grid(NT,NQ);
    qmain<<<grid,256,SM_TOT>>>(b1,b2,W3,b3,out);
}

// round 8
// speedup vs baseline: 3.5154x; 3.5154x over previous
#include <cuda_runtime.h>
#include <cuda_fp16.h>
#include <stdint.h>

#define NQ 10
#define BSZ 32768
#define NT 256

__device__ __half g_X [2][NT][8192];      // [dig][tile][128r x 64k, sw128]
__device__ __half g_W1[2][NQ][16384];     // [dig][net][256c x 64k, sw128]
__device__ __half g_W2[NQ][2][4][8192];   // [net][np][kc][128n x 64k, sw128]

__device__ __forceinline__ uint32_t smem_u32(const void* p){
    uint32_t a; asm("{ .reg .u64 t; cvta.to.shared.u64 t, %1; cvt.u32.u64 %0, t; }":"=r"(a):"l"(p)); return a;
}
__device__ __forceinline__ uint32_t sw128(uint32_t o){ return o ^ ((o>>3)&0x70); }
__device__ __forceinline__ void cpa16(uint32_t d, const void* s){
    asm volatile("cp.async.cg.shared.global [%0], [%1], 16;"::"r"(d),"l"(s):"memory");
}
#define CP_COMMIT() asm volatile("cp.async.commit_group;":::"memory")
#define CP_WAIT(n)  asm volatile("cp.async.wait_group %0;"::"n"(n):"memory")
__device__ __forceinline__ void ldm4(uint32_t r[4], uint32_t a){
    asm volatile("ldmatrix.sync.aligned.m8n8.x4.shared.b16 {%0,%1,%2,%3}, [%4];"
        :"=r"(r[0]),"=r"(r[1]),"=r"(r[2]),"=r"(r[3]):"r"(a));
}
__device__ __forceinline__ void hmma(float c[4], const uint32_t a[4], uint32_t b0, uint32_t b1){
    asm volatile("mma.sync.aligned.m16n8k16.row.col.f32.f16.f16.f32 "
        "{%0,%1,%2,%3},{%4,%5,%6,%7},{%8,%9},{%0,%1,%2,%3};"
        :"+f"(c[0]),"+f"(c[1]),"+f"(c[2]),"+f"(c[3])
        :"r"(a[0]),"r"(a[1]),"r"(a[2]),"r"(a[3]),"r"(b0),"r"(b1));
}
// fp32 pair -> fp16 hi word + fp16 residual word
__device__ __forceinline__ void split2f(float v0, float v1, uint32_t& hw, uint32_t& lw){
    __half h0=__float2half_rn(v0), h1=__float2half_rn(v1);
    hw=(uint32_t)__half_as_ushort(h0)|((uint32_t)__half_as_ushort(h1)<<16);
    __half g0=__float2half_rn(v0-__half2float(h0)), g1=__float2half_rn(v1-__half2float(h1));
    lw=(uint32_t)__half_as_ushort(g0)|((uint32_t)__half_as_ushort(g1)<<16);
}
__device__ __forceinline__ uint32_t h2(float v0, float v1){
    __half h0=__float2half_rn(v0), h1=__float2half_rn(v1);
    return (uint32_t)__half_as_ushort(h0)|((uint32_t)__half_as_ushort(h1)<<16);
}

// ===================== prep =====================
__global__ void __launch_bounds__(128) prep_x(const float* __restrict__ st, const float* __restrict__ ac){
    int t=blockIdx.x, r=threadIdx.x, R=t*128+r;
    uint32_t wh[32], wl[32];
    #pragma unroll
    for(int i=0;i<32;i++){wh[i]=0;wl[i]=0;}
    #pragma unroll
    for(int kp=0;kp<12;kp++){
        int k=kp*2;
        float v0=0.f,v1=0.f;
        if(k<17)v0=st[R*17+k]; else if(k<23)v0=ac[R*6+k-17];
        if(k+1<17)v1=st[R*17+k+1]; else if(k+1<23)v1=ac[R*6+k+1-17];
        split2f(v0,v1,wh[kp],wl[kp]);
    }
    char* dh=(char*)&g_X[0][t][0]; char* dl=(char*)&g_X[1][t][0];
    #pragma unroll
    for(int u=0;u<8;u++){
        uint32_t off=sw128((uint32_t)(r*128+u*16));
        *(uint4*)(dh+off)=make_uint4(wh[4*u],wh[4*u+1],wh[4*u+2],wh[4*u+3]);
        *(uint4*)(dl+off)=make_uint4(wl[4*u],wl[4*u+1],wl[4*u+2],wl[4*u+3]);
    }
}
__global__ void __launch_bounds__(256) prep_w1(const float* __restrict__ W1){
    int n=blockIdx.x, c=threadIdx.x;
    uint32_t wh[32], wl[32];
    #pragma unroll
    for(int i=0;i<32;i++){wh[i]=0;wl[i]=0;}
    #pragma unroll
    for(int kp=0;kp<12;kp++){
        int k=kp*2;
        float v0=(k<23)?W1[(n*23+k)*256+c]:0.f;
        float v1=(k+1<23)?W1[(n*23+k+1)*256+c]:0.f;
        split2f(v0,v1,wh[kp],wl[kp]);
    }
    char* dh=(char*)&g_W1[0][n][0]; char* dl=(char*)&g_W1[1][n][0];
    #pragma unroll
    for(int u=0;u<8;u++){
        uint32_t off=sw128((uint32_t)(c*128+u*16));
        *(uint4*)(dh+off)=make_uint4(wh[4*u],wh[4*u+1],wh[4*u+2],wh[4*u+3]);
        *(uint4*)(dl+off)=make_uint4(wl[4*u],wl[4*u+1],wl[4*u+2],wl[4*u+3]);
    }
}
__global__ void __launch_bounds__(128) prep_w2(const float* __restrict__ W2){
    int n=blockIdx.x>>1, np=blockIdx.x&1, nl=threadIdx.x;
    const float* src=W2+n*65536+np*128+nl;
    for(int kc=0;kc<4;kc++){
        uint32_t w[32];
        #pragma unroll
        for(int kp=0;kp<32;kp++){
            int k=kc*64+kp*2;
            w[kp]=h2(src[k*256],src[(k+1)*256]);
        }
        char* d=(char*)&g_W2[n][np][kc][0];
        #pragma unroll
        for(int u=0;u<8;u++){
            uint32_t off=sw128((uint32_t)(nl*128+u*16));
            *(uint4*)(d+off)=make_uint4(w[4*u],w[4*u+1],w[4*u+2],w[4*u+3]);
        }
    }
}

// ===================== main =====================
// Phase2: A2H [4kc x 16K] @0, A2L @65536, ring 3x16K @131072, misc @180224.
// Phase1 overlay: Xh@0, Xl@16384, W1h@32768(32K), W1l@65536(32K).
#define SM_A2H  0
#define SM_XH   0
#define SM_XL   16384
#define SM_W1H  32768
#define SM_A2L  65536
#define SM_W1L  65536
#define SM_RING 131072
#define SM_B1   180224
#define SM_B2   181248
#define SM_W3   182272
#define SM_RED  183296
#define SM_TOT  184320

__global__ void __launch_bounds__(256,1)
qmain(const float* __restrict__ b1,const float* __restrict__ b2,
      const float* __restrict__ W3,const float* __restrict__ b3,float* __restrict__ out){
    extern __shared__ char sm[];
    float* f=(float*)sm;
    const uint32_t sb=smem_u32(sm);
    const int tid=threadIdx.x, wid=tid>>5, lane=tid&31;
    const int tile=blockIdx.x, n=blockIdx.y;
    const int wm=wid&3, wn=wid>>2, Rw=wm*32;
    const int aRow=(lane&7)+((lane>>3)&1)*8, aCol=(lane>>4)*8;
    const int bRow=(lane&7)+((lane>>4)<<3),  bCol=((lane>>3)&1)*8;
    const int q=lane>>2, s2=(lane&3)*2;

    // stage Xh,Xl (16K each) + W1h,W1l (32K each)
    {
        const char* xh=(const char*)&g_X[0][tile][0];
        const char* xl=(const char*)&g_X[1][tile][0];
        for(int i=tid;i<1024;i+=256){ cpa16(sb+SM_XH+i*16,xh+i*16); cpa16(sb+SM_XL+i*16,xl+i*16); }
        const char* wh=(const char*)&g_W1[0][n][0];
        const char* wl=(const char*)&g_W1[1][n][0];
        for(int i=tid;i<2048;i+=256){ cpa16(sb+SM_W1H+i*16,wh+i*16); cpa16(sb+SM_W1L+i*16,wl+i*16); }
        CP_COMMIT();
    }
    f[SM_B1/4+tid]=b1[n*256+tid];
    f[SM_B2/4+tid]=b2[n*256+tid];
    f[SM_W3/4+tid]=W3[n*256+tid];
    CP_WAIT(0);
    __syncthreads();

    // ---- layer 1: warp 32r x 128c, 3-term fp16 split ----
    float acc1[2][16][4];
    #pragma unroll
    for(int mt=0;mt<2;mt++)
        #pragma unroll
        for(int nt=0;nt<16;nt++)
            #pragma unroll
            for(int e=0;e<4;e++) acc1[mt][nt][e]=0.f;
    #pragma unroll
    for(int ks=0;ks<2;ks++){
        const int k=ks*16;
        uint32_t ah[2][4],al[2][4];
        #pragma unroll
        for(int mt=0;mt<2;mt++){
            uint32_t o=sw128((uint32_t)((Rw+mt*16+aRow)*128+(k+aCol)*2));
            ldm4(ah[mt],sb+SM_XH+o);
            ldm4(al[mt],sb+SM_XL+o);
        }
        #pragma unroll
        for(int p=0;p<8;p++){
            int n0=wn*128+p*16;
            uint32_t ob=sw128((uint32_t)((n0+bRow)*128+(k+bCol)*2));
            uint32_t bh[4],bl[4];
            ldm4(bh,sb+SM_W1H+ob);
            ldm4(bl,sb+SM_W1L+ob);
            #pragma unroll
            for(int mt=0;mt<2;mt++)
                #pragma unroll
                for(int sub=0;sub<2;sub++){
                    int nt=p*2+sub;
                    hmma(acc1[mt][nt],ah[mt],bh[sub*2],bh[sub*2+1]);
                    hmma(acc1[mt][nt],ah[mt],bl[sub*2],bl[sub*2+1]);
                    hmma(acc1[mt][nt],al[mt],bh[sub*2],bh[sub*2+1]);
                }
        }
    }
    __syncthreads();   // X/W1 regions free

    // ring prologue: stages 0,1
    #pragma unroll
    for(int s=0;s<2;s++){
        const char* src=(const char*)&g_W2[n][0][s][0];
        for(int i=tid;i<1024;i+=256) cpa16(sb+SM_RING+(uint32_t)(s*16384)+i*16,src+i*16);
        CP_COMMIT();
    }

    // ---- epilogue 1: relu(acc1+b1) -> fp16 hi/lo A2 images ----
    {
        const float* b1s=f+SM_B1/4;
        #pragma unroll
        for(int mt=0;mt<2;mt++){
            const int r0=Rw+mt*16+q;
            #pragma unroll
            for(int nt=0;nt<16;nt++){
                const int c0=wn*128+nt*8+s2;
                const int chunk=c0>>6, kk=c0&63;
                const float bb0=b1s[c0], bb1=b1s[c0+1];
                uint32_t hw,lw;
                split2f(fmaxf(acc1[mt][nt][0]+bb0,0.f),fmaxf(acc1[mt][nt][1]+bb1,0.f),hw,lw);
                uint32_t off=sw128((uint32_t)(r0*128+kk*2));
                *(uint32_t*)(sm+SM_A2H+chunk*16384+off)=hw;
                *(uint32_t*)(sm+SM_A2L+chunk*16384+off)=lw;
                uint32_t hw2,lw2;
                split2f(fmaxf(acc1[mt][nt][2]+bb0,0.f),fmaxf(acc1[mt][nt][3]+bb1,0.f),hw2,lw2);
                uint32_t off2=sw128((uint32_t)((r0+8)*128+kk*2));
                *(uint32_t*)(sm+SM_A2H+chunk*16384+off2)=hw2;
                *(uint32_t*)(sm+SM_A2L+chunk*16384+off2)=lw2;
            }
        }
    }
    __syncthreads();   // A2 visible

    // ---- layer 2+3: 8 stages (np 0..1 x kc 0..3), 3-deep 16KB ring ----
    float rowsum[4]={0.f,0.f,0.f,0.f};
    float acc[2][8][4];
    #pragma unroll 1
    for(int t=0;t<8;t++){
        const int np=t>>2, kc=t&3;
        if(t<6){
            const char* src=(const char*)&g_W2[n][(t+2)>>2][(t+2)&3][0];
            uint32_t d=sb+SM_RING+(uint32_t)(((t+2)%3)*16384);
            for(int i=tid;i<1024;i+=256) cpa16(d+i*16,src+i*16);
            CP_COMMIT();
            CP_WAIT(2);
        } else if(t==6) CP_WAIT(1); else CP_WAIT(0);
        __syncthreads();

        if(kc==0){
            #pragma unroll
            for(int mt=0;mt<2;mt++)
                #pragma unroll
                for(int nt=0;nt<8;nt++)
                    #pragma unroll
                    for(int e=0;e<4;e++) acc[mt][nt][e]=0.f;
        }
        const uint32_t abh=sb+SM_A2H+(uint32_t)(kc*16384);
        const uint32_t abl=sb+SM_A2L+(uint32_t)(kc*16384);
        const uint32_t ring=sb+SM_RING+(uint32_t)((t%3)*16384);
        #pragma unroll
        for(int ks=0;ks<4;ks++){
            const int k=ks*16;
            uint32_t ah[2][4],al[2][4];
            #pragma unroll
            for(int mt=0;mt<2;mt++){
                uint32_t o=sw128((uint32_t)((Rw+mt*16+aRow)*128+(k+aCol)*2));
                ldm4(ah[mt],abh+o);
                ldm4(al[mt],abl+o);
            }
            #pragma unroll
            for(int p=0;p<4;p++){
                int nl=wn*64+p*16;
                uint32_t ob=sw128((uint32_t)((nl+bRow)*128+(k+bCol)*2));
                uint32_t bf[4];
                ldm4(bf,ring+ob);
                #pragma unroll
                for(int mt=0;mt<2;mt++)
                    #pragma unroll
                    for(int sub=0;sub<2;sub++){
                        int nt=p*2+sub;
                        hmma(acc[mt][nt],ah[mt],bf[sub*2],bf[sub*2+1]);
                        hmma(acc[mt][nt],al[mt],bf[sub*2],bf[sub*2+1]);
                    }
            }
        }
        if(kc==3){
            const float* b2s=f+SM_B2/4;
            const float* w3s=f+SM_W3/4;
            #pragma unroll
            for(int mt=0;mt<2;mt++)
                #pragma unroll
                for(int nt=0;nt<8;nt++){
                    const int c0=np*128+wn*64+nt*8+s2;
                    const float bb0=b2s[c0], bb1=b2s[c0+1];
                    const float u0=w3s[c0], u1=w3s[c0+1];
                    rowsum[mt*2+0]+=fmaxf(acc[mt][nt][0]+bb0,0.f)*u0
                                  +fmaxf(acc[mt][nt][1]+bb1,0.f)*u1;
                    rowsum[mt*2+1]+=fmaxf(acc[mt][nt][2]+bb0,0.f)*u0
                                  +fmaxf(acc[mt][nt][3]+bb1,0.f)*u1;
                }
        }
        __syncthreads();
    }

    #pragma unroll
    for(int i=0;i<4;i++){
        float v=rowsum[i];
        v+=__shfl_xor_sync(0xffffffffu,v,1);
        v+=__shfl_xor_sync(0xffffffffu,v,2);
        if((lane&3)==0) f[SM_RED/4+wn*128+Rw+(i>>1)*16+(i&1)*8+q]=v;
    }
    __syncthreads();
    if(tid<128)
        out[n*BSZ+tile*128+tid]=f[SM_RED/4+tid]+f[SM_RED/4+128+tid]+b3[n];
}

extern "C" void kernel_launch(void* const* d_in, const int* in_sizes, int n_in,
                              void* d_out, int out_size){
    const float* state =(const float*)d_in[0];
    const float* action=(const float*)d_in[1];
    const float* W1=(const float*)d_in[2];
    const float* b1=(const float*)d_in[3];
    const float* W2=(const float*)d_in[4];
    const float* b2=(const float*)d_in[5];
    const float* W3=(const float*)d_in[6];
    const float* b3=(const float*)d_in[7];
    float* out=(float*)d_out;

    prep_x<<<NT,128>>>(state,action);
    prep_w1<<<NQ,256>>>(W1);
    prep_w2<<<NQ*2,128>>>(W2);

    cudaFuncSetAttribute(qmain,cudaFuncAttributeMaxDynamicSharedMemorySize,SM_TOT);
    dim3 grid(NT,NQ);
    qmain<<<grid,256,SM_TOT>>>(b1,b2,W3,b3,out);
}

// round 9
// speedup vs baseline: 3.5720x; 1.0161x over previous
#include <cuda_runtime.h>
#include <cuda_fp16.h>
#include <stdint.h>

#define NQ 10
#define BSZ 32768
#define NT 256

__device__ __half g_X [2][NT][8192];      // [dig][tile][128r x 64k, sw128]
__device__ __half g_W1[2][NQ][16384];     // [dig][net][256c x 64k, sw128]
__device__ __half g_W2[NQ][2][4][8192];   // [net][np][kc][128n x 64k, sw128]

__device__ __forceinline__ uint32_t smem_u32(const void* p){
    uint32_t a; asm("{ .reg .u64 t; cvta.to.shared.u64 t, %1; cvt.u32.u64 %0, t; }":"=r"(a):"l"(p)); return a;
}
__device__ __forceinline__ uint32_t sw128(uint32_t o){ return o ^ ((o>>3)&0x70); }
__device__ __forceinline__ void cpa16(uint32_t d, const void* s){
    asm volatile("cp.async.cg.shared.global [%0], [%1], 16;"::"r"(d),"l"(s):"memory");
}
#define CP_COMMIT() asm volatile("cp.async.commit_group;":::"memory")
#define CP_WAIT(n)  asm volatile("cp.async.wait_group %0;"::"n"(n):"memory")
__device__ __forceinline__ void ldm4(uint32_t r[4], uint32_t a){
    asm volatile("ldmatrix.sync.aligned.m8n8.x4.shared.b16 {%0,%1,%2,%3}, [%4];"
        :"=r"(r[0]),"=r"(r[1]),"=r"(r[2]),"=r"(r[3]):"r"(a));
}
__device__ __forceinline__ void hmma(float c[4], const uint32_t a[4], uint32_t b0, uint32_t b1){
    asm volatile("mma.sync.aligned.m16n8k16.row.col.f32.f16.f16.f32 "
        "{%0,%1,%2,%3},{%4,%5,%6,%7},{%8,%9},{%0,%1,%2,%3};"
        :"+f"(c[0]),"+f"(c[1]),"+f"(c[2]),"+f"(c[3])
        :"r"(a[0]),"r"(a[1]),"r"(a[2]),"r"(a[3]),"r"(b0),"r"(b1));
}
__device__ __forceinline__ void split2f(float v0, float v1, uint32_t& hw, uint32_t& lw){
    __half h0=__float2half_rn(v0), h1=__float2half_rn(v1);
    hw=(uint32_t)__half_as_ushort(h0)|((uint32_t)__half_as_ushort(h1)<<16);
    __half g0=__float2half_rn(v0-__half2float(h0)), g1=__float2half_rn(v1-__half2float(h1));
    lw=(uint32_t)__half_as_ushort(g0)|((uint32_t)__half_as_ushort(g1)<<16);
}
__device__ __forceinline__ uint32_t h2(float v0, float v1){
    __half h0=__float2half_rn(v0), h1=__float2half_rn(v1);
    return (uint32_t)__half_as_ushort(h0)|((uint32_t)__half_as_ushort(h1)<<16);
}

// ===================== prep =====================
__global__ void __launch_bounds__(128) prep_x(const float* __restrict__ st, const float* __restrict__ ac){
    int t=blockIdx.x, r=threadIdx.x, R=t*128+r;
    uint32_t wh[32], wl[32];
    #pragma unroll
    for(int i=0;i<32;i++){wh[i]=0;wl[i]=0;}
    #pragma unroll
    for(int kp=0;kp<12;kp++){
        int k=kp*2;
        float v0=0.f,v1=0.f;
        if(k<17)v0=st[R*17+k]; else if(k<23)v0=ac[R*6+k-17];
        if(k+1<17)v1=st[R*17+k+1]; else if(k+1<23)v1=ac[R*6+k+1-17];
        split2f(v0,v1,wh[kp],wl[kp]);
    }
    char* dh=(char*)&g_X[0][t][0]; char* dl=(char*)&g_X[1][t][0];
    #pragma unroll
    for(int u=0;u<8;u++){
        uint32_t off=sw128((uint32_t)(r*128+u*16));
        *(uint4*)(dh+off)=make_uint4(wh[4*u],wh[4*u+1],wh[4*u+2],wh[4*u+3]);
        *(uint4*)(dl+off)=make_uint4(wl[4*u],wl[4*u+1],wl[4*u+2],wl[4*u+3]);
    }
}
__global__ void __launch_bounds__(256) prep_w1(const float* __restrict__ W1){
    int n=blockIdx.x, c=threadIdx.x;
    uint32_t wh[32], wl[32];
    #pragma unroll
    for(int i=0;i<32;i++){wh[i]=0;wl[i]=0;}
    #pragma unroll
    for(int kp=0;kp<12;kp++){
        int k=kp*2;
        float v0=(k<23)?W1[(n*23+k)*256+c]:0.f;
        float v1=(k+1<23)?W1[(n*23+k+1)*256+c]:0.f;
        split2f(v0,v1,wh[kp],wl[kp]);
    }
    char* dh=(char*)&g_W1[0][n][0]; char* dl=(char*)&g_W1[1][n][0];
    #pragma unroll
    for(int u=0;u<8;u++){
        uint32_t off=sw128((uint32_t)(c*128+u*16));
        *(uint4*)(dh+off)=make_uint4(wh[4*u],wh[4*u+1],wh[4*u+2],wh[4*u+3]);
        *(uint4*)(dl+off)=make_uint4(wl[4*u],wl[4*u+1],wl[4*u+2],wl[4*u+3]);
    }
}
__global__ void __launch_bounds__(128) prep_w2(const float* __restrict__ W2){
    int n=blockIdx.x>>1, np=blockIdx.x&1, nl=threadIdx.x;
    const float* src=W2+n*65536+np*128+nl;
    for(int kc=0;kc<4;kc++){
        uint32_t w[32];
        #pragma unroll
        for(int kp=0;kp<32;kp++){
            int k=kc*64+kp*2;
            w[kp]=h2(src[k*256],src[(k+1)*256]);
        }
        char* d=(char*)&g_W2[n][np][kc][0];
        #pragma unroll
        for(int u=0;u<8;u++){
            uint32_t off=sw128((uint32_t)(nl*128+u*16));
            *(uint4*)(d+off)=make_uint4(w[4*u],w[4*u+1],w[4*u+2],w[4*u+3]);
        }
    }
}

// ===================== main =====================
// Phase2: A2H [4kc x 16K] @0, A2L @65536, ring 4x16K @131072, misc @196608.
// Phase1 overlay: Xh@0, Xl@16384, W1h@32768(32K), W1l@65536(32K).
#define SM_A2H  0
#define SM_XH   0
#define SM_XL   16384
#define SM_W1H  32768
#define SM_A2L  65536
#define SM_W1L  65536
#define SM_RING 131072
#define SM_B1   196608
#define SM_B2   197632
#define SM_W3   198656
#define SM_RED  199680
#define SM_TOT  200704

__global__ void __launch_bounds__(256,1)
qmain(const float* __restrict__ b1,const float* __restrict__ b2,
      const float* __restrict__ W3,const float* __restrict__ b3,float* __restrict__ out){
    extern __shared__ char sm[];
    float* f=(float*)sm;
    const uint32_t sb=smem_u32(sm);
    const int tid=threadIdx.x, wid=tid>>5, lane=tid&31;
    const int tile=blockIdx.x, n=blockIdx.y;
    const int wm=wid&3, wn=wid>>2, Rw=wm*32;
    const int aRow=(lane&7)+((lane>>3)&1)*8, aCol=(lane>>4)*8;
    const int bRow=(lane&7)+((lane>>4)<<3),  bCol=((lane>>3)&1)*8;
    const int q=lane>>2, s2=(lane&3)*2;

    // stage Xh,Xl (16K each) + W1h,W1l (32K each)
    {
        const char* xh=(const char*)&g_X[0][tile][0];
        const char* xl=(const char*)&g_X[1][tile][0];
        for(int i=tid;i<1024;i+=256){ cpa16(sb+SM_XH+i*16,xh+i*16); cpa16(sb+SM_XL+i*16,xl+i*16); }
        const char* wh=(const char*)&g_W1[0][n][0];
        const char* wl=(const char*)&g_W1[1][n][0];
        for(int i=tid;i<2048;i+=256){ cpa16(sb+SM_W1H+i*16,wh+i*16); cpa16(sb+SM_W1L+i*16,wl+i*16); }
        CP_COMMIT();
    }
    f[SM_B1/4+tid]=b1[n*256+tid];
    f[SM_B2/4+tid]=b2[n*256+tid];
    f[SM_W3/4+tid]=W3[n*256+tid];
    CP_WAIT(0);
    __syncthreads();

    // ---- layer 1: warp 32r x 128c, 3-term fp16 split ----
    float acc1[2][16][4];
    #pragma unroll
    for(int mt=0;mt<2;mt++)
        #pragma unroll
        for(int nt=0;nt<16;nt++)
            #pragma unroll
            for(int e=0;e<4;e++) acc1[mt][nt][e]=0.f;
    #pragma unroll
    for(int ks=0;ks<2;ks++){
        const int k=ks*16;
        uint32_t ah[2][4],al[2][4];
        #pragma unroll
        for(int mt=0;mt<2;mt++){
            uint32_t o=sw128((uint32_t)((Rw+mt*16+aRow)*128+(k+aCol)*2));
            ldm4(ah[mt],sb+SM_XH+o);
            ldm4(al[mt],sb+SM_XL+o);
        }
        #pragma unroll
        for(int p=0;p<8;p++){
            int n0=wn*128+p*16;
            uint32_t ob=sw128((uint32_t)((n0+bRow)*128+(k+bCol)*2));
            uint32_t bh[4],bl[4];
            ldm4(bh,sb+SM_W1H+ob);
            ldm4(bl,sb+SM_W1L+ob);
            #pragma unroll
            for(int mt=0;mt<2;mt++)
                #pragma unroll
                for(int sub=0;sub<2;sub++){
                    int nt=p*2+sub;
                    hmma(acc1[mt][nt],ah[mt],bh[sub*2],bh[sub*2+1]);
                    hmma(acc1[mt][nt],ah[mt],bl[sub*2],bl[sub*2+1]);
                    hmma(acc1[mt][nt],al[mt],bh[sub*2],bh[sub*2+1]);
                }
        }
    }
    __syncthreads();   // X/W1 regions free (A2 overlays them)

    // ring prologue: stages 0,1 -> slots 0,1
    #pragma unroll
    for(int s=0;s<2;s++){
        const char* src=(const char*)&g_W2[n][0][s][0];
        for(int i=tid;i<1024;i+=256) cpa16(sb+SM_RING+(uint32_t)(s*16384)+i*16,src+i*16);
        CP_COMMIT();
    }

    // ---- epilogue 1: relu(acc1+b1) -> fp16 hi/lo A2 images ----
    {
        const float* b1s=f+SM_B1/4;
        #pragma unroll
        for(int mt=0;mt<2;mt++){
            const int r0=Rw+mt*16+q;
            #pragma unroll
            for(int nt=0;nt<16;nt++){
                const int c0=wn*128+nt*8+s2;
                const int chunk=c0>>6, kk=c0&63;
                const float bb0=b1s[c0], bb1=b1s[c0+1];
                uint32_t hw,lw;
                split2f(fmaxf(acc1[mt][nt][0]+bb0,0.f),fmaxf(acc1[mt][nt][1]+bb1,0.f),hw,lw);
                uint32_t off=sw128((uint32_t)(r0*128+kk*2));
                *(uint32_t*)(sm+SM_A2H+chunk*16384+off)=hw;
                *(uint32_t*)(sm+SM_A2L+chunk*16384+off)=lw;
                uint32_t hw2,lw2;
                split2f(fmaxf(acc1[mt][nt][2]+bb0,0.f),fmaxf(acc1[mt][nt][3]+bb1,0.f),hw2,lw2);
                uint32_t off2=sw128((uint32_t)((r0+8)*128+kk*2));
                *(uint32_t*)(sm+SM_A2H+chunk*16384+off2)=hw2;
                *(uint32_t*)(sm+SM_A2L+chunk*16384+off2)=lw2;
            }
        }
    }
    __syncthreads();   // A2 visible

    // ---- layer 2+3: 8 stages (np 0..1 x kc 0..3), 4-deep 16KB ring, ONE sync/stage ----
    // WAR safety: prefetch for t+2 -> slot (t+2)%4, last read at stage t-2; the
    // top-of-stage-(t-1) barrier (crossed by all warps) ordered those reads.
    float rowsum[4]={0.f,0.f,0.f,0.f};
    float acc[2][8][4];
    #pragma unroll 1
    for(int t=0;t<8;t++){
        const int np=t>>2, kc=t&3;
        if(t<6){
            const char* src=(const char*)&g_W2[n][(t+2)>>2][(t+2)&3][0];
            uint32_t d=sb+SM_RING+(uint32_t)(((t+2)&3)*16384);
            for(int i=tid;i<1024;i+=256) cpa16(d+i*16,src+i*16);
            CP_COMMIT();
            CP_WAIT(2);
        } else if(t==6) CP_WAIT(1); else CP_WAIT(0);
        __syncthreads();

        if(kc==0){
            #pragma unroll
            for(int mt=0;mt<2;mt++)
                #pragma unroll
                for(int nt=0;nt<8;nt++)
                    #pragma unroll
                    for(int e=0;e<4;e++) acc[mt][nt][e]=0.f;
        }
        const uint32_t abh=sb+SM_A2H+(uint32_t)(kc*16384);
        const uint32_t abl=sb+SM_A2L+(uint32_t)(kc*16384);
        const uint32_t ring=sb+SM_RING+(uint32_t)((t&3)*16384);
        #pragma unroll
        for(int ks=0;ks<4;ks++){
            const int k=ks*16;
            uint32_t ah[2][4],al[2][4];
            #pragma unroll
            for(int mt=0;mt<2;mt++){
                uint32_t o=sw128((uint32_t)((Rw+mt*16+aRow)*128+(k+aCol)*2));
                ldm4(ah[mt],abh+o);
                ldm4(al[mt],abl+o);
            }
            #pragma unroll
            for(int p=0;p<4;p++){
                int nl=wn*64+p*16;
                uint32_t ob=sw128((uint32_t)((nl+bRow)*128+(k+bCol)*2));
                uint32_t bf[4];
                ldm4(bf,ring+ob);
                #pragma unroll
                for(int mt=0;mt<2;mt++)
                    #pragma unroll
                    for(int sub=0;sub<2;sub++){
                        int nt=p*2+sub;
                        hmma(acc[mt][nt],ah[mt],bf[sub*2],bf[sub*2+1]);
                        hmma(acc[mt][nt],al[mt],bf[sub*2],bf[sub*2+1]);
                    }
            }
        }
        if(kc==3){
            const float2* b2v=(const float2*)(f+SM_B2/4);
            const float2* w3v=(const float2*)(f+SM_W3/4);
            #pragma unroll
            for(int mt=0;mt<2;mt++)
                #pragma unroll
                for(int nt=0;nt<8;nt++){
                    const int c0=np*128+wn*64+nt*8+s2;
                    const float2 bb=b2v[c0>>1];
                    const float2 uu=w3v[c0>>1];
                    rowsum[mt*2+0]+=fmaxf(acc[mt][nt][0]+bb.x,0.f)*uu.x
                                  +fmaxf(acc[mt][nt][1]+bb.y,0.f)*uu.y;
                    rowsum[mt*2+1]+=fmaxf(acc[mt][nt][2]+bb.x,0.f)*uu.x
                                  +fmaxf(acc[mt][nt][3]+bb.y,0.f)*uu.y;
                }
        }
    }

    #pragma unroll
    for(int i=0;i<4;i++){
        float v=rowsum[i];
        v+=__shfl_xor_sync(0xffffffffu,v,1);
        v+=__shfl_xor_sync(0xffffffffu,v,2);
        if((lane&3)==0) f[SM_RED/4+wn*128+Rw+(i>>1)*16+(i&1)*8+q]=v;
    }
    __syncthreads();
    if(tid<128)
        out[n*BSZ+tile*128+tid]=f[SM_RED/4+tid]+f[SM_RED/4+128+tid]+b3[n];
}

extern "C" void kernel_launch(void* const* d_in, const int* in_sizes, int n_in,
                              void* d_out, int out_size){
    const float* state =(const float*)d_in[0];
    const float* action=(const float*)d_in[1];
    const float* W1=(const float*)d_in[2];
    const float* b1=(const float*)d_in[3];
    const float* W2=(const float*)d_in[4];
    const float* b2=(const float*)d_in[5];
    const float* W3=(const float*)d_in[6];
    const float* b3=(const float*)d_in[7];
    float* out=(float*)d_out;

    prep_x<<<NT,128>>>(state,action);
    prep_w1<<<NQ,256>>>(W1);
    prep_w2<<<NQ*2,128>>>(W2);

    cudaFuncSetAttribute(qmain,cudaFuncAttributeMaxDynamicSharedMemorySize,SM_TOT);
    dim3 grid(NT,NQ);
    qmain<<<grid,256,SM_TOT>>>(b1,b2,W3,b3,out);
}

// round 10
// speedup vs baseline: 6.3477x; 1.7770x over previous
#include <cuda_runtime.h>
#include <cuda_fp16.h>
#include <stdint.h>

#define NQ 10
#define BSZ 32768
#define NT 256

__device__ __half g_X [2][NT][4096];      // [dig][tile][128r x 32k, 64B rows sw64]
__device__ __half g_W1[NQ][8192];         // [net][256c x 32k, 64B rows sw64]
__device__ __half g_W2[NQ][2][4][8192];   // [net][np][kc][128n x 64k, 128B rows sw128]

__device__ __forceinline__ uint32_t smem_u32(const void* p){
    uint32_t a; asm("{ .reg .u64 t; cvta.to.shared.u64 t, %1; cvt.u32.u64 %0, t; }":"=r"(a):"l"(p)); return a;
}
__device__ __forceinline__ uint32_t sw128(uint32_t o){ return o ^ ((o>>3)&0x70); }
__device__ __forceinline__ uint32_t sw64 (uint32_t o){ return o ^ ((o>>3)&0x30); }
__device__ __forceinline__ void cpa16(uint32_t d, const void* s){
    asm volatile("cp.async.cg.shared.global [%0], [%1], 16;"::"r"(d),"l"(s):"memory");
}
#define CP_COMMIT() asm volatile("cp.async.commit_group;":::"memory")
#define CP_WAIT(n)  asm volatile("cp.async.wait_group %0;"::"n"(n):"memory")
__device__ __forceinline__ void ldm4(uint32_t r[4], uint32_t a){
    asm volatile("ldmatrix.sync.aligned.m8n8.x4.shared.b16 {%0,%1,%2,%3}, [%4];"
        :"=r"(r[0]),"=r"(r[1]),"=r"(r[2]),"=r"(r[3]):"r"(a));
}
__device__ __forceinline__ void hmma(float c[4], const uint32_t a[4], uint32_t b0, uint32_t b1){
    asm volatile("mma.sync.aligned.m16n8k16.row.col.f32.f16.f16.f32 "
        "{%0,%1,%2,%3},{%4,%5,%6,%7},{%8,%9},{%0,%1,%2,%3};"
        :"+f"(c[0]),"+f"(c[1]),"+f"(c[2]),"+f"(c[3])
        :"r"(a[0]),"r"(a[1]),"r"(a[2]),"r"(a[3]),"r"(b0),"r"(b1));
}
__device__ __forceinline__ uint32_t h2(float v0, float v1){
    __half h0=__float2half_rn(v0), h1=__float2half_rn(v1);
    return (uint32_t)__half_as_ushort(h0)|((uint32_t)__half_as_ushort(h1)<<16);
}
__device__ __forceinline__ void split2f(float v0, float v1, uint32_t& hw, uint32_t& lw){
    __half h0=__float2half_rn(v0), h1=__float2half_rn(v1);
    hw=(uint32_t)__half_as_ushort(h0)|((uint32_t)__half_as_ushort(h1)<<16);
    __half g0=__float2half_rn(v0-__half2float(h0)), g1=__float2half_rn(v1-__half2float(h1));
    lw=(uint32_t)__half_as_ushort(g0)|((uint32_t)__half_as_ushort(g1)<<16);
}

// ===================== prep =====================
__global__ void __launch_bounds__(128) prep_x(const float* __restrict__ st, const float* __restrict__ ac){
    int t=blockIdx.x, r=threadIdx.x, R=t*128+r;
    uint32_t wh[16], wl[16];
    #pragma unroll
    for(int i=0;i<16;i++){wh[i]=0;wl[i]=0;}
    #pragma unroll
    for(int kp=0;kp<12;kp++){
        int k=kp*2;
        float v0=0.f,v1=0.f;
        if(k<17)v0=st[R*17+k]; else if(k<23)v0=ac[R*6+k-17];
        if(k+1<17)v1=st[R*17+k+1]; else if(k+1<23)v1=ac[R*6+k+1-17];
        split2f(v0,v1,wh[kp],wl[kp]);
    }
    char* dh=(char*)&g_X[0][t][0]; char* dl=(char*)&g_X[1][t][0];
    #pragma unroll
    for(int u=0;u<4;u++){
        uint32_t off=sw64((uint32_t)(r*64+u*16));
        *(uint4*)(dh+off)=make_uint4(wh[4*u],wh[4*u+1],wh[4*u+2],wh[4*u+3]);
        *(uint4*)(dl+off)=make_uint4(wl[4*u],wl[4*u+1],wl[4*u+2],wl[4*u+3]);
    }
}
__global__ void __launch_bounds__(256) prep_w1(const float* __restrict__ W1){
    int n=blockIdx.x, c=threadIdx.x;
    uint32_t w[16];
    #pragma unroll
    for(int i=0;i<16;i++) w[i]=0;
    #pragma unroll
    for(int kp=0;kp<12;kp++){
        int k=kp*2;
        float v0=(k<23)?W1[(n*23+k)*256+c]:0.f;
        float v1=(k+1<23)?W1[(n*23+k+1)*256+c]:0.f;
        w[kp]=h2(v0,v1);
    }
    char* d=(char*)&g_W1[n][0];
    #pragma unroll
    for(int u=0;u<4;u++){
        uint32_t off=sw64((uint32_t)(c*64+u*16));
        *(uint4*)(d+off)=make_uint4(w[4*u],w[4*u+1],w[4*u+2],w[4*u+3]);
    }
}
__global__ void __launch_bounds__(128) prep_w2(const float* __restrict__ W2){
    int n=blockIdx.x>>1, np=blockIdx.x&1, nl=threadIdx.x;
    const float* src=W2+n*65536+np*128+nl;
    for(int kc=0;kc<4;kc++){
        uint32_t w[32];
        #pragma unroll
        for(int kp=0;kp<32;kp++){
            int k=kc*64+kp*2;
            w[kp]=h2(src[k*256],src[(k+1)*256]);
        }
        char* d=(char*)&g_W2[n][np][kc][0];
        #pragma unroll
        for(int u=0;u<8;u++){
            uint32_t off=sw128((uint32_t)(nl*128+u*16));
            *(uint4*)(d+off)=make_uint4(w[4*u],w[4*u+1],w[4*u+2],w[4*u+3]);
        }
    }
}

// ===================== main =====================
// A2H [4kc x 16K] @0 (64KB). Phase-1 overlay: Xh@0(8K), Xl@8192(8K), W1@16384(16K).
// W2 resident @65536 (128KB: [np][kc] subtiles of 16KB). Misc @196608.
#define SM_A2H 0
#define SM_XH  0
#define SM_XL  8192
#define SM_W1  16384
#define SM_W2  65536
#define SM_B1  196608
#define SM_B2  197632
#define SM_W3  198656
#define SM_RED 199680
#define SM_TOT 200704

__global__ void __launch_bounds__(256,1)
qmain(const float* __restrict__ b1,const float* __restrict__ b2,
      const float* __restrict__ W3,const float* __restrict__ b3,float* __restrict__ out){
    extern __shared__ char sm[];
    float* f=(float*)sm;
    const uint32_t sb=smem_u32(sm);
    const int tid=threadIdx.x, wid=tid>>5, lane=tid&31;
    const int tile=blockIdx.x, n=blockIdx.y;
    const int wm=wid&1, wn=wid>>1, Rw=wm*64;      // 2 m-warps x 4 n-warps; warp rows [Rw,Rw+32)? see below
    // NOTE: wm in {0,1} -> rows wm*32? We want 8 warps = 2m x 4n, 128 rows / 2 = 64 rows per m-warp?
    // Keep previous proven mapping: wm = wid&3 (4 m-warps of 32 rows), wn = wid>>2 (2 n-warps of 128 cols).
    const int wm4=wid&3, wn2=wid>>2;
    const int R0=wm4*32;
    const int aRow=(lane&7)+((lane>>3)&1)*8, aCol=(lane>>4)*8;
    const int bRow=(lane&7)+((lane>>4)<<3),  bCol=((lane>>3)&1)*8;
    const int q=lane>>2, s2=(lane&3)*2;

    // stage Xh,Xl (8K each) + W1 (16K) as group0, then all W2 (128K) as group1
    {
        const char* xh=(const char*)&g_X[0][tile][0];
        const char* xl=(const char*)&g_X[1][tile][0];
        for(int i=tid;i<512;i+=256){ cpa16(sb+SM_XH+i*16,xh+i*16); cpa16(sb+SM_XL+i*16,xl+i*16); }
        const char* w1=(const char*)&g_W1[n][0];
        for(int i=tid;i<1024;i+=256) cpa16(sb+SM_W1+i*16,w1+i*16);
        CP_COMMIT();
        const char* w2=(const char*)&g_W2[n][0][0][0];
        for(int i=tid;i<8192;i+=256) cpa16(sb+SM_W2+i*16,w2+i*16);
        CP_COMMIT();
    }
    f[SM_B1/4+tid]=b1[n*256+tid];
    f[SM_B2/4+tid]=b2[n*256+tid];
    f[SM_W3/4+tid]=W3[n*256+tid];
    CP_WAIT(1);          // X + W1 ready (W2 still in flight)
    __syncthreads();

    // ---- layer 1: warp tile 32r x 128c (wn2 half of N), 2-term (x split, W1 single) ----
    float acc1[2][16][4];
    #pragma unroll
    for(int mt=0;mt<2;mt++)
        #pragma unroll
        for(int nt=0;nt<16;nt++)
            #pragma unroll
            for(int e=0;e<4;e++) acc1[mt][nt][e]=0.f;
    #pragma unroll
    for(int ks=0;ks<2;ks++){
        const int k=ks*16;
        uint32_t ah[2][4],al[2][4];
        #pragma unroll
        for(int mt=0;mt<2;mt++){
            uint32_t o=sw64((uint32_t)((R0+mt*16+aRow)*64+(k+aCol)*2));
            ldm4(ah[mt],sb+SM_XH+o);
            ldm4(al[mt],sb+SM_XL+o);
        }
        #pragma unroll
        for(int p=0;p<8;p++){
            int n0=wn2*128+p*16;
            uint32_t ob=sw64((uint32_t)((n0+bRow)*64+(k+bCol)*2));
            uint32_t bw[4];
            ldm4(bw,sb+SM_W1+ob);
            #pragma unroll
            for(int mt=0;mt<2;mt++)
                #pragma unroll
                for(int sub=0;sub<2;sub++){
                    int nt=p*2+sub;
                    hmma(acc1[mt][nt],ah[mt],bw[sub*2],bw[sub*2+1]);
                    hmma(acc1[mt][nt],al[mt],bw[sub*2],bw[sub*2+1]);
                }
        }
    }
    __syncthreads();   // everyone done reading X/W1; A2H may now overwrite them

    // ---- epilogue 1: relu(acc1+b1) -> fp16 (single) A2 image ----
    {
        const float* b1s=f+SM_B1/4;
        #pragma unroll
        for(int mt=0;mt<2;mt++){
            const int r0=R0+mt*16+q;
            #pragma unroll
            for(int nt=0;nt<16;nt++){
                const int c0=wn2*128+nt*8+s2;
                const int chunk=c0>>6, kk=c0&63;
                const float bb0=b1s[c0], bb1=b1s[c0+1];
                uint32_t hw=h2(fmaxf(acc1[mt][nt][0]+bb0,0.f),fmaxf(acc1[mt][nt][1]+bb1,0.f));
                *(uint32_t*)(sm+SM_A2H+chunk*16384+sw128((uint32_t)(r0*128+kk*2)))=hw;
                uint32_t hw2=h2(fmaxf(acc1[mt][nt][2]+bb0,0.f),fmaxf(acc1[mt][nt][3]+bb1,0.f));
                *(uint32_t*)(sm+SM_A2H+chunk*16384+sw128((uint32_t)((r0+8)*128+kk*2)))=hw2;
            }
        }
    }
    CP_WAIT(0);          // W2 fully resident
    __syncthreads();     // A2 visible

    // ---- layer 2: single straight-line smem loop, 1-term, no barriers ----
    float acc[2][16][4];
    #pragma unroll
    for(int mt=0;mt<2;mt++)
        #pragma unroll
        for(int nt=0;nt<16;nt++)
            #pragma unroll
            for(int e=0;e<4;e++) acc[mt][nt][e]=0.f;

    #pragma unroll 1
    for(int kc=0;kc<4;kc++){
        const uint32_t ab=sb+SM_A2H+(uint32_t)(kc*16384);
        #pragma unroll
        for(int ks=0;ks<4;ks++){
            const int k=ks*16;
            uint32_t ah[2][4];
            #pragma unroll
            for(int mt=0;mt<2;mt++){
                uint32_t o=sw128((uint32_t)((R0+mt*16+aRow)*128+(k+aCol)*2));
                ldm4(ah[mt],ab+o);
            }
            #pragma unroll
            for(int np=0;np<2;np++){
                const uint32_t bbase=sb+SM_W2+(uint32_t)((np*4+kc)*16384);
                #pragma unroll
                for(int p=0;p<2;p++){
                    int nl=wn2*64+p*16;   // wn2 in {0,1}: cols [wn2*64, wn2*64+32)? -> need 64 cols: p<4
                    (void)nl;
                    // handled below with p4 loop
                }
                #pragma unroll
                for(int p4=0;p4<4;p4++){
                    int nl=wn2*64+p4*16;
                    uint32_t ob=sw128((uint32_t)((nl+bRow)*128+(k+bCol)*2));
                    uint32_t bf[4];
                    ldm4(bf,bbase+ob);
                    #pragma unroll
                    for(int mt=0;mt<2;mt++)
                        #pragma unroll
                        for(int sub=0;sub<2;sub++){
                            int nt=np*8+p4*2+sub;
                            hmma(acc[mt][nt],ah[mt],bf[sub*2],bf[sub*2+1]);
                        }
                }
            }
        }
    }

    // ---- layer 3 fold + reduce ----
    float rowsum[4]={0.f,0.f,0.f,0.f};
    {
        const float2* b2v=(const float2*)(f+SM_B2/4);
        const float2* w3v=(const float2*)(f+SM_W3/4);
        #pragma unroll
        for(int mt=0;mt<2;mt++)
            #pragma unroll
            for(int nt=0;nt<16;nt++){
                const int np=nt>>3, ntl=nt&7;
                const int c0=np*128+wn2*64+ntl*8+s2;
                const float2 bb=b2v[c0>>1];
                const float2 uu=w3v[c0>>1];
                rowsum[mt*2+0]+=fmaxf(acc[mt][nt][0]+bb.x,0.f)*uu.x
                              +fmaxf(acc[mt][nt][1]+bb.y,0.f)*uu.y;
                rowsum[mt*2+1]+=fmaxf(acc[mt][nt][2]+bb.x,0.f)*uu.x
                              +fmaxf(acc[mt][nt][3]+bb.y,0.f)*uu.y;
            }
    }
    #pragma unroll
    for(int i=0;i<4;i++){
        float v=rowsum[i];
        v+=__shfl_xor_sync(0xffffffffu,v,1);
        v+=__shfl_xor_sync(0xffffffffu,v,2);
        if((lane&3)==0) f[SM_RED/4+wn2*128+R0+(i>>1)*16+(i&1)*8+q]=v;
    }
    __syncthreads();
    if(tid<128)
        out[n*BSZ+tile*128+tid]=f[SM_RED/4+tid]+f[SM_RED/4+128+tid]+b3[n];
}

extern "C" void kernel_launch(void* const* d_in, const int* in_sizes, int n_in,
                              void* d_out, int out_size){
    const float* state =(const float*)d_in[0];
    const float* action=(const float*)d_in[1];
    const float* W1=(const float*)d_in[2];
    const float* b1=(const float*)d_in[3];
    const float* W2=(const float*)d_in[4];
    const float* b2=(const float*)d_in[5];
    const float* W3=(const float*)d_in[6];
    const float* b3=(const float*)d_in[7];
    float* out=(float*)d_out;

    prep_x<<<NT,128>>>(state,action);
    prep_w1<<<NQ,256>>>(W1);
    prep_w2<<<NQ*2,128>>>(W2);

    cudaFuncSetAttribute(qmain,cudaFuncAttributeMaxDynamicSharedMemorySize,SM_TOT);
    dim3 grid(NT,NQ);
    qmain<<<grid,256,SM_TOT>>>(b1,b2,W3,b3,out);
}